// round 3
// baseline (speedup 1.0000x reference)
#include <cuda_runtime.h>

#define N_ROWS   16384
#define D        1024
#define D4       (D / 4)          // 256 float4 per row
#define TEMPC    0.05f
#define EPSC     1e-8f

#define THREADS       256
#define WARPS_CTA     8
#define ROWS_PER_WARP 2
#define BATCH_ROWS    (WARPS_CTA * ROWS_PER_WARP)   // 16 rows per grab
#define GRID          1184                           // 148 SMs x 8 CTAs
#define F4_PER_LANE   (D4 / 32)                      // 8

__device__ float g_row_loss[N_ROWS];
__device__ unsigned int g_row_counter = 0;
__device__ unsigned int g_done = 0;

__global__ __launch_bounds__(THREADS) void byol_persist_kernel(
    const float4* __restrict__ a4, const float4* __restrict__ b4,
    float* __restrict__ out)
{
    const int t   = threadIdx.x;
    const int wid = t >> 5;
    const int lid = t & 31;

    __shared__ unsigned int s_base;
    __shared__ bool s_last;

    for (;;) {
        if (t == 0) s_base = atomicAdd(&g_row_counter, (unsigned)BATCH_ROWS);
        __syncthreads();
        const unsigned int base = s_base;
        __syncthreads();            // protect s_base before next grab overwrites
        if (base >= N_ROWS) break;

        #pragma unroll
        for (int r = 0; r < ROWS_PER_WARP; r++) {
            const int row = base + wid * ROWS_PER_WARP + r;
            const long idx = (long)row * D4 + lid;

            float4 av[F4_PER_LANE], bv[F4_PER_LANE];
            #pragma unroll
            for (int j = 0; j < F4_PER_LANE; j++) av[j] = __ldcs(&a4[idx + 32 * j]);
            #pragma unroll
            for (int j = 0; j < F4_PER_LANE; j++) bv[j] = __ldcs(&b4[idx + 32 * j]);

            float dot = 0.f, aa = 0.f, bb = 0.f;
            #pragma unroll
            for (int j = 0; j < F4_PER_LANE; j++) {
                dot += av[j].x * bv[j].x + av[j].y * bv[j].y
                     + av[j].z * bv[j].z + av[j].w * bv[j].w;
                aa  += av[j].x * av[j].x + av[j].y * av[j].y
                     + av[j].z * av[j].z + av[j].w * av[j].w;
                bb  += bv[j].x * bv[j].x + bv[j].y * bv[j].y
                     + bv[j].z * bv[j].z + bv[j].w * bv[j].w;
            }

            #pragma unroll
            for (int off = 16; off > 0; off >>= 1) {
                dot += __shfl_xor_sync(0xffffffffu, dot, off);
                aa  += __shfl_xor_sync(0xffffffffu, aa,  off);
                bb  += __shfl_xor_sync(0xffffffffu, bb,  off);
            }

            if (lid == 0) {
                const float n1 = fmaxf(sqrtf(aa), EPSC);
                const float n2 = fmaxf(sqrtf(bb), EPSC);
                g_row_loss[row] = 2.0f - 2.0f * (dot / (n1 * n2));
            }
        }
    }

    // Completion protocol
    __threadfence();
    if (t == 0) {
        const unsigned int prev = atomicAdd(&g_done, 1u);
        s_last = (prev == GRID - 1);
    }
    __syncthreads();

    // Last CTA: deterministic fixed-order reduction of all 16384 row losses
    if (s_last) {
        __shared__ float s[THREADS];
        float sum = 0.f;
        #pragma unroll 16
        for (int i = 0; i < N_ROWS / THREADS; i++)     // 64 each, fixed order
            sum += g_row_loss[t + i * THREADS];
        s[t] = sum;
        __syncthreads();
        #pragma unroll
        for (int off = THREADS / 2; off > 0; off >>= 1) {
            if (t < off) s[t] += s[t + off];
            __syncthreads();
        }
        if (t == 0) {
            out[0] = s[0] / ((float)N_ROWS * TEMPC);
            g_done = 0;          // reset for graph replay
            g_row_counter = 0;
        }
    }
}

extern "C" void kernel_launch(void* const* d_in, const int* in_sizes, int n_in,
                              void* d_out, int out_size)
{
    const float4* a4 = (const float4*)d_in[0];  // online_output [16384,1024] f32
    const float4* b4 = (const float4*)d_in[1];  // target_output [16384,1024] f32
    float* out = (float*)d_out;

    byol_persist_kernel<<<GRID, THREADS>>>(a4, b4, out);
}

// round 5
// speedup vs baseline: 1.0467x; 1.0467x over previous
#include <cuda_runtime.h>

#define N_ROWS   16384
#define D        1024
#define D4       (D / 4)          // 256 float4 per row
#define TEMPC    0.05f
#define EPSC     1e-8f

#define THREADS     256
#define WARPS_CTA   8
#define GRID        1184          // 148 SMs x 8 CTAs: one perfectly balanced wave
#define F4_PER_LANE (D4 / 32)     // 8

__device__ float g_partial[GRID];
__device__ unsigned int g_done = 0;

__global__ __launch_bounds__(THREADS) void byol_balanced_kernel(
    const float4* __restrict__ a4, const float4* __restrict__ b4,
    float* __restrict__ out)
{
    const int t   = threadIdx.x;
    const int wid = t >> 5;
    const int lid = t & 31;

    // Contiguous, near-even row partition: 13 or 14 rows per CTA
    const int start = (int)(((long)blockIdx.x * N_ROWS) / GRID);
    const int end   = (int)(((long)(blockIdx.x + 1) * N_ROWS) / GRID);

    float loss = 0.f;   // accumulated on lane 0 of each warp

    for (int row = start + wid; row < end; row += WARPS_CTA) {
        const long idx = (long)row * D4 + lid;

        float4 av[F4_PER_LANE], bv[F4_PER_LANE];
        #pragma unroll
        for (int j = 0; j < F4_PER_LANE; j++) av[j] = a4[idx + 32 * j];
        #pragma unroll
        for (int j = 0; j < F4_PER_LANE; j++) bv[j] = b4[idx + 32 * j];

        float dot = 0.f, aa = 0.f, bb = 0.f;
        #pragma unroll
        for (int j = 0; j < F4_PER_LANE; j++) {
            dot += av[j].x * bv[j].x + av[j].y * bv[j].y
                 + av[j].z * bv[j].z + av[j].w * bv[j].w;
            aa  += av[j].x * av[j].x + av[j].y * av[j].y
                 + av[j].z * av[j].z + av[j].w * av[j].w;
            bb  += bv[j].x * bv[j].x + bv[j].y * bv[j].y
                 + bv[j].z * bv[j].z + bv[j].w * bv[j].w;
        }

        #pragma unroll
        for (int off = 16; off > 0; off >>= 1) {
            dot += __shfl_xor_sync(0xffffffffu, dot, off);
            aa  += __shfl_xor_sync(0xffffffffu, aa,  off);
            bb  += __shfl_xor_sync(0xffffffffu, bb,  off);
        }

        if (lid == 0) {
            const float n1 = fmaxf(sqrtf(aa), EPSC);
            const float n2 = fmaxf(sqrtf(bb), EPSC);
            loss += 2.0f - 2.0f * (dot / (n1 * n2));
        }
    }

    // CTA combine (fixed warp order -> deterministic), one partial per CTA
    __shared__ float s_warp[WARPS_CTA];
    __shared__ bool  s_last;
    if (lid == 0) s_warp[wid] = loss;
    __syncthreads();

    if (t == 0) {
        float p = 0.f;
        #pragma unroll
        for (int w = 0; w < WARPS_CTA; w++) p += s_warp[w];
        g_partial[blockIdx.x] = p;
        __threadfence();
        const unsigned int prev = atomicAdd(&g_done, 1u);
        s_last = (prev == GRID - 1);
    }
    __syncthreads();

    // Last CTA: deterministic fixed-order reduce of 1184 partials
    if (s_last) {
        __shared__ float s[THREADS];
        float sum = 0.f;
        #pragma unroll
        for (int i = 0; i < (GRID + THREADS - 1) / THREADS; i++) {
            const int k = t + i * THREADS;
            if (k < GRID) sum += g_partial[k];
        }
        s[t] = sum;
        __syncthreads();
        #pragma unroll
        for (int off = THREADS / 2; off > 0; off >>= 1) {
            if (t < off) s[t] += s[t + off];
            __syncthreads();
        }
        if (t == 0) {
            out[0] = s[0] / ((float)N_ROWS * TEMPC);
            g_done = 0;   // reset for graph replay
        }
    }
}

extern "C" void kernel_launch(void* const* d_in, const int* in_sizes, int n_in,
                              void* d_out, int out_size)
{
    const float4* a4 = (const float4*)d_in[0];  // online_output [16384,1024] f32
    const float4* b4 = (const float4*)d_in[1];  // target_output [16384,1024] f32
    float* out = (float*)d_out;

    byol_balanced_kernel<<<GRID, THREADS>>>(a4, b4, out);
}

// round 6
// speedup vs baseline: 1.1263x; 1.0760x over previous
#include <cuda_runtime.h>

#define N_ROWS   16384
#define D        1024
#define D4       (D / 4)          // 256 float4 per row
#define TEMPC    0.05f
#define EPSC     1e-8f

#define THREADS     256
#define WARPS_CTA   8
#define GRID        (N_ROWS / WARPS_CTA)   // 2048 CTAs, exactly 1 row per warp
#define F4_PER_LANE (D4 / 32)              // 8

__device__ float g_partial[GRID];
__device__ unsigned int g_done = 0;

__global__ __launch_bounds__(THREADS) void byol_finegrain_kernel(
    const float4* __restrict__ a4, const float4* __restrict__ b4,
    float* __restrict__ out)
{
    const int t   = threadIdx.x;
    const int wid = t >> 5;
    const int lid = t & 31;

    // Exactly one row per warp: uniform work at every granularity
    const int  row = blockIdx.x * WARPS_CTA + wid;
    const long idx = (long)row * D4 + lid;

    float4 av[F4_PER_LANE], bv[F4_PER_LANE];
    #pragma unroll
    for (int j = 0; j < F4_PER_LANE; j++) av[j] = a4[idx + 32 * j];
    #pragma unroll
    for (int j = 0; j < F4_PER_LANE; j++) bv[j] = b4[idx + 32 * j];

    float dot = 0.f, aa = 0.f, bb = 0.f;
    #pragma unroll
    for (int j = 0; j < F4_PER_LANE; j++) {
        dot += av[j].x * bv[j].x + av[j].y * bv[j].y
             + av[j].z * bv[j].z + av[j].w * bv[j].w;
        aa  += av[j].x * av[j].x + av[j].y * av[j].y
             + av[j].z * av[j].z + av[j].w * av[j].w;
        bb  += bv[j].x * bv[j].x + bv[j].y * bv[j].y
             + bv[j].z * bv[j].z + bv[j].w * bv[j].w;
    }

    #pragma unroll
    for (int off = 16; off > 0; off >>= 1) {
        dot += __shfl_xor_sync(0xffffffffu, dot, off);
        aa  += __shfl_xor_sync(0xffffffffu, aa,  off);
        bb  += __shfl_xor_sync(0xffffffffu, bb,  off);
    }

    // CTA combine (fixed warp order -> deterministic), one partial per CTA
    __shared__ float s_warp[WARPS_CTA];
    __shared__ bool  s_last;
    if (lid == 0) {
        const float n1 = fmaxf(sqrtf(aa), EPSC);
        const float n2 = fmaxf(sqrtf(bb), EPSC);
        s_warp[wid] = 2.0f - 2.0f * (dot / (n1 * n2));
    }
    __syncthreads();

    if (t == 0) {
        float p = 0.f;
        #pragma unroll
        for (int w = 0; w < WARPS_CTA; w++) p += s_warp[w];
        g_partial[blockIdx.x] = p;
        __threadfence();
        const unsigned int prev = atomicAdd(&g_done, 1u);
        s_last = (prev == GRID - 1);
    }
    __syncthreads();

    // Last CTA: deterministic fixed-order reduce of 2048 partials
    if (s_last) {
        __shared__ float s[THREADS];
        float sum = 0.f;
        #pragma unroll
        for (int i = 0; i < GRID / THREADS; i++)       // 8 each, fixed order
            sum += g_partial[t + i * THREADS];
        s[t] = sum;
        __syncthreads();
        #pragma unroll
        for (int off = THREADS / 2; off > 0; off >>= 1) {
            if (t < off) s[t] += s[t + off];
            __syncthreads();
        }
        if (t == 0) {
            out[0] = s[0] / ((float)N_ROWS * TEMPC);
            g_done = 0;   // reset for graph replay
        }
    }
}

extern "C" void kernel_launch(void* const* d_in, const int* in_sizes, int n_in,
                              void* d_out, int out_size)
{
    const float4* a4 = (const float4*)d_in[0];  // online_output [16384,1024] f32
    const float4* b4 = (const float4*)d_in[1];  // target_output [16384,1024] f32
    float* out = (float*)d_out;

    byol_finegrain_kernel<<<GRID, THREADS>>>(a4, b4, out);
}